// round 1
// baseline (speedup 1.0000x reference)
#include <cuda_runtime.h>
#include <cuda_bf16.h>
#include <math.h>

// Problem constants
#define B_   512
#define S_   512
#define D_   960
#define H1   480   // D/2
#define H2   240   // D/4
#define MH   256   // B/2

// Scratch (device globals; no allocations allowed)
__device__ __align__(16) float g_pooled[B_ * D_];     // [512,960]
__device__ __align__(16) float g_h[B_ * H1];          // [512,480]
__device__ __align__(16) float g_z[B_ * H2];          // [512,240]
__device__ __align__(16) float g_zT[H2 * B_];         // [240,512]
__device__ __align__(16) float g_sim[B_ * B_];        // [512,512]
__device__ __align__(16) float g_norm[B_];
__device__ __align__(16) float g_nll[B_];

// ---------------------------------------------------------------------------
// Kernel 1: mean-pool over S.  One block per batch row, float4 columns.
// ---------------------------------------------------------------------------
__global__ __launch_bounds__(256) void pool_kernel(const float* __restrict__ x) {
    int b = blockIdx.x;
    int t = threadIdx.x;
    if (t >= D_ / 4) return;  // 240 active threads
    const float4* xb = reinterpret_cast<const float4*>(x) + (size_t)b * S_ * (D_ / 4);
    float4 acc = make_float4(0.f, 0.f, 0.f, 0.f);
#pragma unroll 4
    for (int s = 0; s < S_; s++) {
        float4 v = xb[(size_t)s * (D_ / 4) + t];
        acc.x += v.x; acc.y += v.y; acc.z += v.z; acc.w += v.w;
    }
    const float inv = 1.0f / (float)S_;
    float4 r = make_float4(acc.x * inv, acc.y * inv, acc.z * inv, acc.w * inv);
    reinterpret_cast<float4*>(g_pooled)[(size_t)b * (D_ / 4) + t] = r;
}

// ---------------------------------------------------------------------------
// Kernel 2: generic tiled fp32 GEMM  C = act(A @ W + bias)
//   64x64 tile, BK=16, 256 threads, 4x4 per-thread microtile.
//   blockIdx.z selects the (A-offset, W, bias, C-offset) "half" for the MLPs.
//   Optionally also writes C^T (used by layer 2 to produce zT).
//   M multiple of 64; N only needs N%4==0 (guarded); K multiple of 16.
// ---------------------------------------------------------------------------
#define BM 64
#define BN 64
#define BK 16

__global__ __launch_bounds__(256) void gemm64(
    const float* __restrict__ Abase,
    const float* __restrict__ W0, const float* __restrict__ W1,
    const float* __restrict__ bias0, const float* __restrict__ bias1,
    float* __restrict__ Cbase, float* __restrict__ CT,
    int Mh, int K, int N, int ldCT, int relu)
{
    const int half = blockIdx.z;
    const float* A    = Abase + (size_t)half * Mh * K;
    const float* W    = half ? W1 : W0;
    const float* bias = half ? bias1 : bias0;
    float* C          = Cbase + (size_t)half * Mh * N;
    const int rowOffT = half * Mh;

    __shared__ float As[BK][BM];
    __shared__ float Ws[BK][BN];

    const int tid = threadIdx.x;       // 256
    const int tx = tid & 15;           // 0..15
    const int ty = tid >> 4;           // 0..15
    const int bm = blockIdx.y * BM;
    const int bn = blockIdx.x * BN;

    // load-index mapping
    const int aRow  = tid >> 2;        // 0..63
    const int aCol4 = tid & 3;         // float4 idx within BK
    const int wRow  = tid >> 4;        // 0..15
    const int wCol4 = tid & 15;        // float4 idx within BN

    float acc[4][4];
#pragma unroll
    for (int i = 0; i < 4; i++)
#pragma unroll
        for (int j = 0; j < 4; j++) acc[i][j] = 0.f;

    for (int k0 = 0; k0 < K; k0 += BK) {
        // A tile: BM x BK  (store transposed into As[k][m])
        {
            float4 v = *reinterpret_cast<const float4*>(
                &A[(size_t)(bm + aRow) * K + k0 + aCol4 * 4]);
            As[aCol4 * 4 + 0][aRow] = v.x;
            As[aCol4 * 4 + 1][aRow] = v.y;
            As[aCol4 * 4 + 2][aRow] = v.z;
            As[aCol4 * 4 + 3][aRow] = v.w;
        }
        // W tile: BK x BN
        {
            int n = bn + wCol4 * 4;
            float4 v = make_float4(0.f, 0.f, 0.f, 0.f);
            if (n < N)
                v = *reinterpret_cast<const float4*>(&W[(size_t)(k0 + wRow) * N + n]);
            *reinterpret_cast<float4*>(&Ws[wRow][wCol4 * 4]) = v;
        }
        __syncthreads();

#pragma unroll
        for (int kk = 0; kk < BK; kk++) {
            float a[4], b[4];
#pragma unroll
            for (int i = 0; i < 4; i++) a[i] = As[kk][ty * 4 + i];
#pragma unroll
            for (int j = 0; j < 4; j++) b[j] = Ws[kk][tx * 4 + j];
#pragma unroll
            for (int i = 0; i < 4; i++)
#pragma unroll
                for (int j = 0; j < 4; j++)
                    acc[i][j] = fmaf(a[i], b[j], acc[i][j]);
        }
        __syncthreads();
    }

    // epilogue
#pragma unroll
    for (int i = 0; i < 4; i++) {
        int row = bm + ty * 4 + i;
#pragma unroll
        for (int j = 0; j < 4; j++) {
            int n = bn + tx * 4 + j;
            if (n < N) {
                float v = acc[i][j];
                if (bias) v += bias[n];
                if (relu) v = fmaxf(v, 0.f);
                C[(size_t)row * N + n] = v;
                if (CT) CT[(size_t)n * ldCT + rowOffT + row] = v;
            }
        }
    }
}

// ---------------------------------------------------------------------------
// Kernel 3: norms from the sim diagonal (sim[i][i] = ||z_i||^2)
// ---------------------------------------------------------------------------
__global__ void diag_kernel() {
    int j = threadIdx.x;  // 512 threads
    g_norm[j] = sqrtf(g_sim[(size_t)j * B_ + j]);
}

// ---------------------------------------------------------------------------
// Kernel 4: per-row cosine + temperature + logsumexp + positive pair
// One block (256 threads) per row; 2 logits per thread.
// ---------------------------------------------------------------------------
__global__ __launch_bounds__(256) void lse_kernel() {
    const int i = blockIdx.x;
    const int t = threadIdx.x;
    __shared__ float red[256];

    const float ni = g_norm[i];
    float l[2];
#pragma unroll
    for (int u = 0; u < 2; u++) {
        int j = t + u * 256;
        float denom = fmaxf(ni * g_norm[j], 1e-8f);
        float c = g_sim[(size_t)i * B_ + j] / denom;
        l[u] = (j == i) ? (-65504.0f / 0.1f) : (c / 0.1f);
    }

    // block max
    float m = fmaxf(l[0], l[1]);
    red[t] = m;
    __syncthreads();
    for (int s = 128; s > 0; s >>= 1) {
        if (t < s) red[t] = fmaxf(red[t], red[t + s]);
        __syncthreads();
    }
    const float mx = red[0];
    __syncthreads();

    // block sum of exp
    float e = expf(l[0] - mx) + expf(l[1] - mx);
    red[t] = e;
    __syncthreads();
    for (int s = 128; s > 0; s >>= 1) {
        if (t < s) red[t] += red[t + s];
        __syncthreads();
    }

    if (t == 0) {
        float lse = mx + logf(red[0]);
        int pc = (i + MH) & (B_ - 1);   // (i - B/2) mod B
        float denom = fmaxf(ni * g_norm[pc], 1e-8f);
        float pos = (g_sim[(size_t)i * B_ + pc] / denom) / 0.1f;
        g_nll[i] = lse - pos;
    }
}

// ---------------------------------------------------------------------------
// Kernel 5: deterministic mean over 512 nll values -> scalar output
// ---------------------------------------------------------------------------
__global__ void mean_kernel(float* __restrict__ out) {
    __shared__ float red[512];
    int t = threadIdx.x;  // 512 threads
    red[t] = g_nll[t];
    __syncthreads();
    for (int s = 256; s > 0; s >>= 1) {
        if (t < s) red[t] += red[t + s];
        __syncthreads();
    }
    if (t == 0) out[0] = red[0] / (float)B_;
}

// ---------------------------------------------------------------------------
extern "C" void kernel_launch(void* const* d_in, const int* in_sizes, int n_in,
                              void* d_out, int out_size) {
    const float* x   = (const float*)d_in[0];
    const float* W1c = (const float*)d_in[1];
    const float* b1c = (const float*)d_in[2];
    const float* W2c = (const float*)d_in[3];
    const float* b2c = (const float*)d_in[4];
    const float* W1a = (const float*)d_in[5];
    const float* b1a = (const float*)d_in[6];
    const float* W2a = (const float*)d_in[7];
    const float* b2a = (const float*)d_in[8];
    float* out = (float*)d_out;

    float *p_pooled, *p_h, *p_z, *p_zT, *p_sim;
    cudaGetSymbolAddress((void**)&p_pooled, g_pooled);
    cudaGetSymbolAddress((void**)&p_h, g_h);
    cudaGetSymbolAddress((void**)&p_z, g_z);
    cudaGetSymbolAddress((void**)&p_zT, g_zT);
    cudaGetSymbolAddress((void**)&p_sim, g_sim);

    // 1. mean pooling: [512,512,960] -> [512,960]
    pool_kernel<<<B_, 256>>>(x);

    // 2. layer 1: h = relu(pooled @ W1 + b1), split halves via blockIdx.z
    //    M=256/half, K=960, N=480  -> grid (ceil(480/64)=8, 256/64=4, 2)
    gemm64<<<dim3(8, 4, 2), 256>>>(p_pooled, W1c, W1a, b1c, b1a,
                                   p_h, nullptr, MH, D_, H1, 0, 1);

    // 3. layer 2: z = h @ W2 + b2 (also writes zT[240,512])
    //    M=256/half, K=480, N=240 -> grid (4, 4, 2)
    gemm64<<<dim3(4, 4, 2), 256>>>(p_h, W2c, W2a, b2c, b2a,
                                   p_z, p_zT, MH, H1, H2, B_, 0);

    // 4. sim = z @ zT : M=512, K=240, N=512 -> grid (8, 8, 1)
    gemm64<<<dim3(8, 8, 1), 256>>>(p_z, p_zT, p_zT, nullptr, nullptr,
                                   p_sim, nullptr, B_, H2, B_, 0, 0);

    // 5. norms from diagonal
    diag_kernel<<<1, B_>>>();

    // 6. per-row logsumexp + positive pair
    lse_kernel<<<B_, 256>>>();

    // 7. mean -> scalar
    mean_kernel<<<1, B_>>>(out);
}

// round 2
// speedup vs baseline: 1.1838x; 1.1838x over previous
#include <cuda_runtime.h>
#include <cuda_bf16.h>
#include <math.h>

// Problem constants
#define B_   512
#define S_   512
#define D_   960
#define H1   480   // D/2
#define H2   240   // D/4
#define MH   256   // B/2
#define D4   240   // D/4 float4s per row
#define SPLIT 4
#define SCHUNK (S_ / SPLIT)   // 128

// Scratch (device globals; no allocations allowed)
__device__ __align__(16) float g_pp[SPLIT * B_ * D_];  // pooling partials [4][512][960]
__device__ __align__(16) float g_pooled[B_ * D_];      // [512,960]
__device__ __align__(16) float g_h[B_ * H1];           // [512,480]
__device__ __align__(16) float g_z[B_ * H2];           // [512,240]
__device__ __align__(16) float g_zT[H2 * B_];          // [240,512]
__device__ __align__(16) float g_sim[B_ * B_];         // [512,512]
__device__ __align__(16) float g_norm[B_];
__device__ __align__(16) float g_nll[B_];

// ---------------------------------------------------------------------------
// Kernel 1a: partial mean-pool. Grid (B, SPLIT); each block sums SCHUNK rows.
// ---------------------------------------------------------------------------
__global__ __launch_bounds__(256) void pool_kernel(const float* __restrict__ x) {
    const int b = blockIdx.x;
    const int c = blockIdx.y;
    const int t = threadIdx.x;
    if (t >= D4) return;  // 240 active threads
    const float4* xb = reinterpret_cast<const float4*>(x)
                     + ((size_t)b * S_ + (size_t)c * SCHUNK) * D4 + t;
    float4 acc = make_float4(0.f, 0.f, 0.f, 0.f);
#pragma unroll 8
    for (int s = 0; s < SCHUNK; s++) {
        float4 v = xb[(size_t)s * D4];
        acc.x += v.x; acc.y += v.y; acc.z += v.z; acc.w += v.w;
    }
    reinterpret_cast<float4*>(g_pp)[((size_t)c * B_ + b) * D4 + t] = acc;
}

// ---------------------------------------------------------------------------
// Kernel 1b: reduce the SPLIT partials, scale by 1/S.
// ---------------------------------------------------------------------------
__global__ __launch_bounds__(256) void pool_reduce_kernel() {
    const int b = blockIdx.x;
    const int t = threadIdx.x;
    if (t >= D4) return;
    const float4* pp = reinterpret_cast<const float4*>(g_pp);
    float4 acc = make_float4(0.f, 0.f, 0.f, 0.f);
#pragma unroll
    for (int c = 0; c < SPLIT; c++) {
        float4 v = pp[((size_t)c * B_ + b) * D4 + t];
        acc.x += v.x; acc.y += v.y; acc.z += v.z; acc.w += v.w;
    }
    const float inv = 1.0f / (float)S_;
    float4 r = make_float4(acc.x * inv, acc.y * inv, acc.z * inv, acc.w * inv);
    reinterpret_cast<float4*>(g_pooled)[(size_t)b * D4 + t] = r;
}

// ---------------------------------------------------------------------------
// Kernel 2: tiled fp32 GEMM  C = act(A @ W + bias), 32x64 tile, BK=16,
// 128 threads, 4x4 microtile, DOUBLE-BUFFERED smem with register prefetch.
// blockIdx.z selects the half (codon/amino). Optionally writes C^T.
// M%32==0, K%16==0; N guarded (N%4==0 required).
// ---------------------------------------------------------------------------
#define BM 32
#define BN 64
#define BK 16

__global__ __launch_bounds__(128) void gemm_k(
    const float* __restrict__ Abase,
    const float* __restrict__ W0, const float* __restrict__ W1,
    const float* __restrict__ bias0, const float* __restrict__ bias1,
    float* __restrict__ Cbase, float* __restrict__ CT,
    int Mh, int K, int N, int ldCT, int relu)
{
    __shared__ float As[2][BK][BM];
    __shared__ float Ws[2][BK][BN];

    const int half = blockIdx.z;
    const float* A    = Abase + (size_t)half * Mh * K;
    const float* W    = half ? W1 : W0;
    const float* bias = half ? bias1 : bias0;
    float* C          = Cbase + (size_t)half * Mh * N;
    const int rowOffT = half * Mh;

    const int tid = threadIdx.x;       // 128
    const int tx = tid & 15;           // 0..15 -> 64 cols (4 each)
    const int ty = tid >> 4;           // 0..7  -> 32 rows (4 each)
    const int bm = blockIdx.y * BM;
    const int bn = blockIdx.x * BN;

    // load mapping
    const int aRow = tid >> 2;         // 0..31
    const int aC4  = tid & 3;          // float4 within BK
    const int wR   = tid >> 4;         // 0..7 (and +8)
    const int wC   = (tid & 15) * 4;   // 0..60

    float acc[4][4];
#pragma unroll
    for (int i = 0; i < 4; i++)
#pragma unroll
        for (int j = 0; j < 4; j++) acc[i][j] = 0.f;

    const bool wOk = (bn + wC) < N;

    // prologue: stage 0
    float4 av = *reinterpret_cast<const float4*>(&A[(size_t)(bm + aRow) * K + aC4 * 4]);
    float4 wv0 = make_float4(0.f, 0.f, 0.f, 0.f), wv1 = wv0;
    if (wOk) {
        wv0 = *reinterpret_cast<const float4*>(&W[(size_t)wR * N + bn + wC]);
        wv1 = *reinterpret_cast<const float4*>(&W[(size_t)(wR + 8) * N + bn + wC]);
    }
    As[0][aC4 * 4 + 0][aRow] = av.x;
    As[0][aC4 * 4 + 1][aRow] = av.y;
    As[0][aC4 * 4 + 2][aRow] = av.z;
    As[0][aC4 * 4 + 3][aRow] = av.w;
    *reinterpret_cast<float4*>(&Ws[0][wR][wC])     = wv0;
    *reinterpret_cast<float4*>(&Ws[0][wR + 8][wC]) = wv1;
    __syncthreads();

    const int nk = K / BK;
    for (int t = 0; t < nk; t++) {
        const int cur = t & 1, nxt = cur ^ 1;
        const bool hasNext = (t + 1) < nk;
        if (hasNext) {
            const int k0 = (t + 1) * BK;
            av = *reinterpret_cast<const float4*>(&A[(size_t)(bm + aRow) * K + k0 + aC4 * 4]);
            wv0 = make_float4(0.f, 0.f, 0.f, 0.f); wv1 = wv0;
            if (wOk) {
                wv0 = *reinterpret_cast<const float4*>(&W[(size_t)(k0 + wR) * N + bn + wC]);
                wv1 = *reinterpret_cast<const float4*>(&W[(size_t)(k0 + wR + 8) * N + bn + wC]);
            }
        }
#pragma unroll
        for (int kk = 0; kk < BK; kk++) {
            float4 a = *reinterpret_cast<const float4*>(&As[cur][kk][ty * 4]);
            float4 b = *reinterpret_cast<const float4*>(&Ws[cur][kk][tx * 4]);
            float ar[4] = {a.x, a.y, a.z, a.w};
            float br[4] = {b.x, b.y, b.z, b.w};
#pragma unroll
            for (int i = 0; i < 4; i++)
#pragma unroll
                for (int j = 0; j < 4; j++)
                    acc[i][j] = fmaf(ar[i], br[j], acc[i][j]);
        }
        if (hasNext) {
            As[nxt][aC4 * 4 + 0][aRow] = av.x;
            As[nxt][aC4 * 4 + 1][aRow] = av.y;
            As[nxt][aC4 * 4 + 2][aRow] = av.z;
            As[nxt][aC4 * 4 + 3][aRow] = av.w;
            *reinterpret_cast<float4*>(&Ws[nxt][wR][wC])     = wv0;
            *reinterpret_cast<float4*>(&Ws[nxt][wR + 8][wC]) = wv1;
        }
        __syncthreads();
    }

    // epilogue
#pragma unroll
    for (int i = 0; i < 4; i++) {
        int row = bm + ty * 4 + i;
#pragma unroll
        for (int j = 0; j < 4; j++) {
            int n = bn + tx * 4 + j;
            if (n < N) {
                float v = acc[i][j];
                if (bias) v += bias[n];
                if (relu) v = fmaxf(v, 0.f);
                C[(size_t)row * N + n] = v;
                if (CT) CT[(size_t)n * ldCT + rowOffT + row] = v;
            }
        }
    }
}

// ---------------------------------------------------------------------------
// Kernel 3: norms from the sim diagonal (sim[i][i] = ||z_i||^2)
// ---------------------------------------------------------------------------
__global__ void diag_kernel() {
    int j = threadIdx.x;  // 512 threads
    g_norm[j] = sqrtf(g_sim[(size_t)j * B_ + j]);
}

// ---------------------------------------------------------------------------
// Kernel 4: per-row cosine + temperature + logsumexp + positive pair
// ---------------------------------------------------------------------------
__global__ __launch_bounds__(256) void lse_kernel() {
    const int i = blockIdx.x;
    const int t = threadIdx.x;
    __shared__ float red[256];

    const float ni = g_norm[i];
    float l[2];
#pragma unroll
    for (int u = 0; u < 2; u++) {
        int j = t + u * 256;
        float denom = fmaxf(ni * g_norm[j], 1e-8f);
        float c = g_sim[(size_t)i * B_ + j] / denom;
        l[u] = (j == i) ? (-65504.0f / 0.1f) : (c / 0.1f);
    }

    float m = fmaxf(l[0], l[1]);
    red[t] = m;
    __syncthreads();
    for (int s = 128; s > 0; s >>= 1) {
        if (t < s) red[t] = fmaxf(red[t], red[t + s]);
        __syncthreads();
    }
    const float mx = red[0];
    __syncthreads();

    float e = expf(l[0] - mx) + expf(l[1] - mx);
    red[t] = e;
    __syncthreads();
    for (int s = 128; s > 0; s >>= 1) {
        if (t < s) red[t] += red[t + s];
        __syncthreads();
    }

    if (t == 0) {
        float lse = mx + logf(red[0]);
        int pc = (i + MH) & (B_ - 1);   // (i - B/2) mod B
        float denom = fmaxf(ni * g_norm[pc], 1e-8f);
        float pos = (g_sim[(size_t)i * B_ + pc] / denom) / 0.1f;
        g_nll[i] = lse - pos;
    }
}

// ---------------------------------------------------------------------------
// Kernel 5: deterministic mean over 512 nll values -> scalar output
// ---------------------------------------------------------------------------
__global__ void mean_kernel(float* __restrict__ out) {
    __shared__ float red[512];
    int t = threadIdx.x;  // 512 threads
    red[t] = g_nll[t];
    __syncthreads();
    for (int s = 256; s > 0; s >>= 1) {
        if (t < s) red[t] += red[t + s];
        __syncthreads();
    }
    if (t == 0) out[0] = red[0] / (float)B_;
}

// ---------------------------------------------------------------------------
extern "C" void kernel_launch(void* const* d_in, const int* in_sizes, int n_in,
                              void* d_out, int out_size) {
    const float* x   = (const float*)d_in[0];
    const float* W1c = (const float*)d_in[1];
    const float* b1c = (const float*)d_in[2];
    const float* W2c = (const float*)d_in[3];
    const float* b2c = (const float*)d_in[4];
    const float* W1a = (const float*)d_in[5];
    const float* b1a = (const float*)d_in[6];
    const float* W2a = (const float*)d_in[7];
    const float* b2a = (const float*)d_in[8];
    float* out = (float*)d_out;

    float *p_pooled, *p_h, *p_z, *p_zT, *p_sim;
    cudaGetSymbolAddress((void**)&p_pooled, g_pooled);
    cudaGetSymbolAddress((void**)&p_h, g_h);
    cudaGetSymbolAddress((void**)&p_z, g_z);
    cudaGetSymbolAddress((void**)&p_zT, g_zT);
    cudaGetSymbolAddress((void**)&p_sim, g_sim);

    // 1. mean pooling: split-S partials, then reduce
    pool_kernel<<<dim3(B_, SPLIT), 256>>>(x);
    pool_reduce_kernel<<<B_, 256>>>();

    // 2. layer 1: h = relu(pooled @ W1 + b1)   M=256x2, K=960, N=480
    gemm_k<<<dim3(8, 8, 2), 128>>>(p_pooled, W1c, W1a, b1c, b1a,
                                   p_h, nullptr, MH, D_, H1, 0, 1);

    // 3. layer 2: z = h @ W2 + b2 (also writes zT)  M=256x2, K=480, N=240
    gemm_k<<<dim3(4, 8, 2), 128>>>(p_h, W2c, W2a, b2c, b2a,
                                   p_z, p_zT, MH, H1, H2, B_, 0);

    // 4. sim = z @ zT : M=512, K=240, N=512
    gemm_k<<<dim3(8, 16, 1), 128>>>(p_z, p_zT, p_zT, nullptr, nullptr,
                                    p_sim, nullptr, B_, H2, B_, 0, 0);

    // 5-7. epilogue
    diag_kernel<<<1, B_>>>();
    lse_kernel<<<B_, 256>>>();
    mean_kernel<<<1, B_>>>(out);
}

// round 3
// speedup vs baseline: 1.3289x; 1.1226x over previous
#include <cuda_runtime.h>
#include <cuda_bf16.h>
#include <math.h>

// Problem constants
#define B_   512
#define S_   512
#define D_   960
#define H1   480   // D/2
#define H2   240   // D/4
#define MH   256   // B/2
#define D4   240   // D/4 float4s per row
#define SPLIT 4
#define SCHUNK (S_ / SPLIT)   // 128

// Scratch (device globals; no allocations allowed)
__device__ __align__(16) float g_pp[SPLIT * B_ * D_];   // pooling partials
__device__ __align__(16) float g_pooled[B_ * D_];       // [512,960]
__device__ __align__(16) float g_part[5 * B_ * H1];     // split-K partials (max KS*M*N = 5*512*480? L1 uses 4*512*480)
__device__ __align__(16) float g_h[B_ * H1];            // [512,480]
__device__ __align__(16) float g_z[B_ * H2];            // [512,240]
__device__ __align__(16) float g_zT[H2 * B_];           // [240,512]
__device__ __align__(16) float g_sim[B_ * B_];          // [512,512]
__device__ __align__(16) float g_norm[B_];
__device__ __align__(16) float g_nll[B_];

// ---------------------------------------------------------------------------
// Kernel 1a: partial mean-pool. Grid (B, SPLIT); each block sums SCHUNK rows.
// ---------------------------------------------------------------------------
__global__ __launch_bounds__(256) void pool_kernel(const float* __restrict__ x) {
    const int b = blockIdx.x;
    const int c = blockIdx.y;
    const int t = threadIdx.x;
    if (t >= D4) return;  // 240 active threads
    const float4* xb = reinterpret_cast<const float4*>(x)
                     + ((size_t)b * S_ + (size_t)c * SCHUNK) * D4 + t;
    float4 acc = make_float4(0.f, 0.f, 0.f, 0.f);
#pragma unroll 8
    for (int s = 0; s < SCHUNK; s++) {
        float4 v = xb[(size_t)s * D4];
        acc.x += v.x; acc.y += v.y; acc.z += v.z; acc.w += v.w;
    }
    reinterpret_cast<float4*>(g_pp)[((size_t)c * B_ + b) * D4 + t] = acc;
}

// ---------------------------------------------------------------------------
// Kernel 1b: reduce the SPLIT partials, scale by 1/S.
// ---------------------------------------------------------------------------
__global__ __launch_bounds__(256) void pool_reduce_kernel() {
    const int b = blockIdx.x;
    const int t = threadIdx.x;
    if (t >= D4) return;
    const float4* pp = reinterpret_cast<const float4*>(g_pp);
    float4 acc = make_float4(0.f, 0.f, 0.f, 0.f);
#pragma unroll
    for (int c = 0; c < SPLIT; c++) {
        float4 v = pp[((size_t)c * B_ + b) * D4 + t];
        acc.x += v.x; acc.y += v.y; acc.z += v.z; acc.w += v.w;
    }
    const float inv = 1.0f / (float)S_;
    float4 r = make_float4(acc.x * inv, acc.y * inv, acc.z * inv, acc.w * inv);
    reinterpret_cast<float4*>(g_pooled)[(size_t)b * D4 + t] = r;
}

// ---------------------------------------------------------------------------
// Kernel 2: split-K tiled fp32 GEMM partials.
//   Cpart[ks][row][n] = A[half][rows, ksKc:(ks+1)Kc] @ W[half][same K range, n]
//   64x64 tile, BK=16, 256 threads, 4x4 microtile, double-buffered smem.
//   blockIdx.z = half * KS + ks.
//   M%64==0, Kc%16==0; N guarded (N%4==0).
// ---------------------------------------------------------------------------
#define BM 64
#define BN 64
#define BK 16
#define AP 68   // padded A pitch (floats) to soften store bank conflicts

__global__ __launch_bounds__(256) void gemm_splitk(
    const float* __restrict__ Abase,
    const float* __restrict__ W0, const float* __restrict__ W1,
    float* __restrict__ Cpart,
    int Mh, int Ktot, int N, int Kc, int KS)
{
    __shared__ float As[2][BK][AP];
    __shared__ float Ws[2][BK][BN];

    const int half = blockIdx.z / KS;
    const int ks   = blockIdx.z % KS;
    const int halves = gridDim.z / KS;
    const int Mtot = halves * Mh;
    const float* A = Abase + (size_t)half * Mh * Ktot + (size_t)ks * Kc;
    const float* W = (half ? W1 : W0) + (size_t)ks * Kc * N;
    float* Cp = Cpart + ((size_t)ks * Mtot + (size_t)half * Mh) * N;

    const int tid = threadIdx.x;       // 256
    const int tx = tid & 15;           // 16 col-groups of 4
    const int ty = tid >> 4;           // 16 row-groups of 4
    const int bm = blockIdx.y * BM;
    const int bn = blockIdx.x * BN;

    const int aRow = tid >> 2;         // 0..63
    const int aC4  = tid & 3;          // float4 idx in BK
    const int wR   = tid >> 4;         // 0..15
    const int wC   = (tid & 15) * 4;   // 0..60

    float acc[4][4];
#pragma unroll
    for (int i = 0; i < 4; i++)
#pragma unroll
        for (int j = 0; j < 4; j++) acc[i][j] = 0.f;

    const bool wOk = (bn + wC) < N;

    // prologue: stage 0
    float4 av = *reinterpret_cast<const float4*>(&A[(size_t)(bm + aRow) * Ktot + aC4 * 4]);
    float4 wv = make_float4(0.f, 0.f, 0.f, 0.f);
    if (wOk) wv = *reinterpret_cast<const float4*>(&W[(size_t)wR * N + bn + wC]);
    As[0][aC4 * 4 + 0][aRow] = av.x;
    As[0][aC4 * 4 + 1][aRow] = av.y;
    As[0][aC4 * 4 + 2][aRow] = av.z;
    As[0][aC4 * 4 + 3][aRow] = av.w;
    *reinterpret_cast<float4*>(&Ws[0][wR][wC]) = wv;
    __syncthreads();

    const int nk = Kc / BK;
    for (int t = 0; t < nk; t++) {
        const int cur = t & 1, nxt = cur ^ 1;
        const bool hasNext = (t + 1) < nk;
        if (hasNext) {
            const int k0 = (t + 1) * BK;
            av = *reinterpret_cast<const float4*>(&A[(size_t)(bm + aRow) * Ktot + k0 + aC4 * 4]);
            wv = make_float4(0.f, 0.f, 0.f, 0.f);
            if (wOk) wv = *reinterpret_cast<const float4*>(&W[(size_t)(k0 + wR) * N + bn + wC]);
        }
#pragma unroll
        for (int kk = 0; kk < BK; kk++) {
            float4 a = *reinterpret_cast<const float4*>(&As[cur][kk][ty * 4]);
            float4 b = *reinterpret_cast<const float4*>(&Ws[cur][kk][tx * 4]);
            float ar[4] = {a.x, a.y, a.z, a.w};
            float br[4] = {b.x, b.y, b.z, b.w};
#pragma unroll
            for (int i = 0; i < 4; i++)
#pragma unroll
                for (int j = 0; j < 4; j++)
                    acc[i][j] = fmaf(ar[i], br[j], acc[i][j]);
        }
        if (hasNext) {
            As[nxt][aC4 * 4 + 0][aRow] = av.x;
            As[nxt][aC4 * 4 + 1][aRow] = av.y;
            As[nxt][aC4 * 4 + 2][aRow] = av.z;
            As[nxt][aC4 * 4 + 3][aRow] = av.w;
            *reinterpret_cast<float4*>(&Ws[nxt][wR][wC]) = wv;
        }
        __syncthreads();
    }

#pragma unroll
    for (int i = 0; i < 4; i++) {
        int row = bm + ty * 4 + i;
#pragma unroll
        for (int j = 0; j < 4; j++) {
            int n = bn + tx * 4 + j;
            if (n < N) Cp[(size_t)row * N + n] = acc[i][j];
        }
    }
}

// ---------------------------------------------------------------------------
// Kernel 3: split-K reduce + bias + relu (+ optional transpose, norm extract).
// One float4 output per thread.
// ---------------------------------------------------------------------------
__global__ __launch_bounds__(256) void reduce_k(
    const float* __restrict__ Cpart, float* __restrict__ C, float* __restrict__ CT,
    const float* __restrict__ bias0, const float* __restrict__ bias1,
    int Mtot, int Mh, int N, int KS, int ldCT, int relu, int writeNorm)
{
    int idx = blockIdx.x * 256 + threadIdx.x;          // float4 index
    int e = idx * 4;
    if (e >= Mtot * N) return;
    int row = e / N;
    int n = e % N;

    float4 acc = make_float4(0.f, 0.f, 0.f, 0.f);
    for (int ks = 0; ks < KS; ks++) {
        float4 v = *reinterpret_cast<const float4*>(&Cpart[((size_t)ks * Mtot + row) * N + n]);
        acc.x += v.x; acc.y += v.y; acc.z += v.z; acc.w += v.w;
    }
    if (bias0) {
        const float* bias = (row < Mh) ? bias0 : bias1;
        float4 bv = *reinterpret_cast<const float4*>(&bias[n]);
        acc.x += bv.x; acc.y += bv.y; acc.z += bv.z; acc.w += bv.w;
    }
    if (relu) {
        acc.x = fmaxf(acc.x, 0.f); acc.y = fmaxf(acc.y, 0.f);
        acc.z = fmaxf(acc.z, 0.f); acc.w = fmaxf(acc.w, 0.f);
    }
    *reinterpret_cast<float4*>(&C[(size_t)row * N + n]) = acc;
    if (CT) {
        CT[(size_t)(n + 0) * ldCT + row] = acc.x;
        CT[(size_t)(n + 1) * ldCT + row] = acc.y;
        CT[(size_t)(n + 2) * ldCT + row] = acc.z;
        CT[(size_t)(n + 3) * ldCT + row] = acc.w;
    }
    if (writeNorm && n <= row && row < n + 4) {
        float d = (row == n) ? acc.x : (row == n + 1) ? acc.y : (row == n + 2) ? acc.z : acc.w;
        g_norm[row] = sqrtf(d);
    }
}

// ---------------------------------------------------------------------------
// Kernel 4: per-row cosine + temperature + logsumexp + positive pair
// ---------------------------------------------------------------------------
__global__ __launch_bounds__(256) void lse_kernel() {
    const int i = blockIdx.x;
    const int t = threadIdx.x;
    __shared__ float red[256];

    const float ni = g_norm[i];
    float l[2];
#pragma unroll
    for (int u = 0; u < 2; u++) {
        int j = t + u * 256;
        float denom = fmaxf(ni * g_norm[j], 1e-8f);
        float c = g_sim[(size_t)i * B_ + j] / denom;
        l[u] = (j == i) ? (-65504.0f / 0.1f) : (c / 0.1f);
    }

    float m = fmaxf(l[0], l[1]);
    red[t] = m;
    __syncthreads();
    for (int s = 128; s > 0; s >>= 1) {
        if (t < s) red[t] = fmaxf(red[t], red[t + s]);
        __syncthreads();
    }
    const float mx = red[0];
    __syncthreads();

    float e = expf(l[0] - mx) + expf(l[1] - mx);
    red[t] = e;
    __syncthreads();
    for (int s = 128; s > 0; s >>= 1) {
        if (t < s) red[t] += red[t + s];
        __syncthreads();
    }

    if (t == 0) {
        float lse = mx + logf(red[0]);
        int pc = (i + MH) & (B_ - 1);   // (i - B/2) mod B
        float denom = fmaxf(ni * g_norm[pc], 1e-8f);
        float pos = (g_sim[(size_t)i * B_ + pc] / denom) / 0.1f;
        g_nll[i] = lse - pos;
    }
}

// ---------------------------------------------------------------------------
// Kernel 5: deterministic mean over 512 nll values -> scalar output
// ---------------------------------------------------------------------------
__global__ void mean_kernel(float* __restrict__ out) {
    __shared__ float red[512];
    int t = threadIdx.x;  // 512 threads
    red[t] = g_nll[t];
    __syncthreads();
    for (int s = 256; s > 0; s >>= 1) {
        if (t < s) red[t] += red[t + s];
        __syncthreads();
    }
    if (t == 0) out[0] = red[0] / (float)B_;
}

// ---------------------------------------------------------------------------
extern "C" void kernel_launch(void* const* d_in, const int* in_sizes, int n_in,
                              void* d_out, int out_size) {
    const float* x   = (const float*)d_in[0];
    const float* W1c = (const float*)d_in[1];
    const float* b1c = (const float*)d_in[2];
    const float* W2c = (const float*)d_in[3];
    const float* b2c = (const float*)d_in[4];
    const float* W1a = (const float*)d_in[5];
    const float* b1a = (const float*)d_in[6];
    const float* W2a = (const float*)d_in[7];
    const float* b2a = (const float*)d_in[8];
    float* out = (float*)d_out;

    float *p_pooled, *p_part, *p_h, *p_z, *p_zT, *p_sim;
    cudaGetSymbolAddress((void**)&p_pooled, g_pooled);
    cudaGetSymbolAddress((void**)&p_part, g_part);
    cudaGetSymbolAddress((void**)&p_h, g_h);
    cudaGetSymbolAddress((void**)&p_z, g_z);
    cudaGetSymbolAddress((void**)&p_zT, g_zT);
    cudaGetSymbolAddress((void**)&p_sim, g_sim);

    // 1. mean pooling
    pool_kernel<<<dim3(B_, SPLIT), 256>>>(x);
    pool_reduce_kernel<<<B_, 256>>>();

    // 2. layer 1: h = relu(pooled @ W1 + b1). M=256x2, K=960 (KS=4, Kc=240), N=480
    gemm_splitk<<<dim3(8, 4, 2 * 4), 256>>>(p_pooled, W1c, W1a, p_part,
                                            MH, D_, H1, 240, 4);
    reduce_k<<<(B_ * H1 / 4 + 255) / 256, 256>>>(p_part, p_h, nullptr, b1c, b1a,
                                                 B_, MH, H1, 4, 0, 1, 0);

    // 3. layer 2: z = h @ W2 + b2 (+ zT). M=256x2, K=480 (KS=5, Kc=96), N=240
    gemm_splitk<<<dim3(4, 4, 2 * 5), 256>>>(p_h, W2c, W2a, p_part,
                                            MH, H1, H2, 96, 5);
    reduce_k<<<(B_ * H2 / 4 + 255) / 256, 256>>>(p_part, p_z, p_zT, b2c, b2a,
                                                 B_, MH, H2, 5, B_, 0, 0);

    // 4. sim = z @ zT. M=512, K=240 (KS=3, Kc=80), N=512. Norms folded in.
    gemm_splitk<<<dim3(8, 8, 1 * 3), 256>>>(p_z, p_zT, p_zT, p_part,
                                            B_, H2, B_, 80, 3);
    reduce_k<<<(B_ * B_ / 4 + 255) / 256, 256>>>(p_part, p_sim, nullptr, nullptr, nullptr,
                                                 B_, B_, B_, 3, 0, 0, 1);

    // 5-6. epilogue
    lse_kernel<<<B_, 256>>>();
    mean_kernel<<<1, B_>>>(out);
}

// round 4
// speedup vs baseline: 1.3843x; 1.0417x over previous
#include <cuda_runtime.h>
#include <cuda_bf16.h>
#include <math.h>

// Problem constants
#define B_   512
#define S_   512
#define D_   960
#define H1   480   // D/2
#define H2   240   // D/4
#define MH   256   // B/2
#define D4   240   // D/4 float4s per row
#define SPLIT 8
#define SCHUNK (S_ / SPLIT)   // 64

// Scratch (device globals; no allocations allowed)
__device__ __align__(16) float g_pp[SPLIT * B_ * D_];   // pooling partials
__device__ __align__(16) float g_pooled[B_ * D_];       // [512,960]
__device__ __align__(16) float g_part[5 * B_ * H1];     // split-K partials
__device__ __align__(16) float g_h[B_ * H1];            // [512,480]
__device__ __align__(16) float g_z[B_ * H2];            // [512,240]
__device__ __align__(16) float g_zT[H2 * B_];           // [240,512]
__device__ __align__(16) float g_sim[B_ * B_];          // [512,512]
__device__ __align__(16) float g_norm[B_];
__device__ __align__(16) float g_nll[B_];

// ---------------------------------------------------------------------------
// Kernel 1a: partial mean-pool. Grid (B, SPLIT); each block sums SCHUNK rows.
// Streaming loads (x is read once; keep it out of L2), dual accumulators.
// ---------------------------------------------------------------------------
__global__ __launch_bounds__(256) void pool_kernel(const float* __restrict__ x) {
    const int b = blockIdx.x;
    const int c = blockIdx.y;
    const int t = threadIdx.x;
    if (t >= D4) return;  // 240 active threads
    const float4* xb = reinterpret_cast<const float4*>(x)
                     + ((size_t)b * S_ + (size_t)c * SCHUNK) * D4 + t;
    float4 a0 = make_float4(0.f, 0.f, 0.f, 0.f);
    float4 a1 = make_float4(0.f, 0.f, 0.f, 0.f);
#pragma unroll 4
    for (int s = 0; s < SCHUNK; s += 2) {
        float4 v0 = __ldcs(&xb[(size_t)s * D4]);
        float4 v1 = __ldcs(&xb[(size_t)(s + 1) * D4]);
        a0.x += v0.x; a0.y += v0.y; a0.z += v0.z; a0.w += v0.w;
        a1.x += v1.x; a1.y += v1.y; a1.z += v1.z; a1.w += v1.w;
    }
    float4 r = make_float4(a0.x + a1.x, a0.y + a1.y, a0.z + a1.z, a0.w + a1.w);
    reinterpret_cast<float4*>(g_pp)[((size_t)c * B_ + b) * D4 + t] = r;
}

// ---------------------------------------------------------------------------
// Kernel 1b: reduce the SPLIT partials, scale by 1/S.
// ---------------------------------------------------------------------------
__global__ __launch_bounds__(256) void pool_reduce_kernel() {
    const int b = blockIdx.x;
    const int t = threadIdx.x;
    if (t >= D4) return;
    const float4* pp = reinterpret_cast<const float4*>(g_pp);
    float4 acc = make_float4(0.f, 0.f, 0.f, 0.f);
#pragma unroll
    for (int c = 0; c < SPLIT; c++) {
        float4 v = pp[((size_t)c * B_ + b) * D4 + t];
        acc.x += v.x; acc.y += v.y; acc.z += v.z; acc.w += v.w;
    }
    const float inv = 1.0f / (float)S_;
    float4 r = make_float4(acc.x * inv, acc.y * inv, acc.z * inv, acc.w * inv);
    reinterpret_cast<float4*>(g_pooled)[(size_t)b * D4 + t] = r;
}

// ---------------------------------------------------------------------------
// Kernel 2: split-K tiled fp32 GEMM partials.
//   64x64 tile, BK=16, 256 threads, 4x4 microtile, double-buffered smem.
//   blockIdx.z = half * KS + ks.
// ---------------------------------------------------------------------------
#define BM 64
#define BN 64
#define BK 16
#define AP 68   // padded A pitch

__global__ __launch_bounds__(256) void gemm_splitk(
    const float* __restrict__ Abase,
    const float* __restrict__ W0, const float* __restrict__ W1,
    float* __restrict__ Cpart,
    int Mh, int Ktot, int N, int Kc, int KS)
{
    __shared__ float As[2][BK][AP];
    __shared__ float Ws[2][BK][BN];

    const int half = blockIdx.z / KS;
    const int ks   = blockIdx.z % KS;
    const int halves = gridDim.z / KS;
    const int Mtot = halves * Mh;
    const float* A = Abase + (size_t)half * Mh * Ktot + (size_t)ks * Kc;
    const float* W = (half ? W1 : W0) + (size_t)ks * Kc * N;
    float* Cp = Cpart + ((size_t)ks * Mtot + (size_t)half * Mh) * N;

    const int tid = threadIdx.x;
    const int tx = tid & 15;
    const int ty = tid >> 4;
    const int bm = blockIdx.y * BM;
    const int bn = blockIdx.x * BN;

    const int aRow = tid >> 2;
    const int aC4  = tid & 3;
    const int wR   = tid >> 4;
    const int wC   = (tid & 15) * 4;

    float acc[4][4];
#pragma unroll
    for (int i = 0; i < 4; i++)
#pragma unroll
        for (int j = 0; j < 4; j++) acc[i][j] = 0.f;

    const bool wOk = (bn + wC) < N;

    float4 av = *reinterpret_cast<const float4*>(&A[(size_t)(bm + aRow) * Ktot + aC4 * 4]);
    float4 wv = make_float4(0.f, 0.f, 0.f, 0.f);
    if (wOk) wv = *reinterpret_cast<const float4*>(&W[(size_t)wR * N + bn + wC]);
    As[0][aC4 * 4 + 0][aRow] = av.x;
    As[0][aC4 * 4 + 1][aRow] = av.y;
    As[0][aC4 * 4 + 2][aRow] = av.z;
    As[0][aC4 * 4 + 3][aRow] = av.w;
    *reinterpret_cast<float4*>(&Ws[0][wR][wC]) = wv;
    __syncthreads();

    const int nk = Kc / BK;
    for (int t = 0; t < nk; t++) {
        const int cur = t & 1, nxt = cur ^ 1;
        const bool hasNext = (t + 1) < nk;
        if (hasNext) {
            const int k0 = (t + 1) * BK;
            av = *reinterpret_cast<const float4*>(&A[(size_t)(bm + aRow) * Ktot + k0 + aC4 * 4]);
            wv = make_float4(0.f, 0.f, 0.f, 0.f);
            if (wOk) wv = *reinterpret_cast<const float4*>(&W[(size_t)(k0 + wR) * N + bn + wC]);
        }
#pragma unroll
        for (int kk = 0; kk < BK; kk++) {
            float4 a = *reinterpret_cast<const float4*>(&As[cur][kk][ty * 4]);
            float4 b = *reinterpret_cast<const float4*>(&Ws[cur][kk][tx * 4]);
            float ar[4] = {a.x, a.y, a.z, a.w};
            float br[4] = {b.x, b.y, b.z, b.w};
#pragma unroll
            for (int i = 0; i < 4; i++)
#pragma unroll
                for (int j = 0; j < 4; j++)
                    acc[i][j] = fmaf(ar[i], br[j], acc[i][j]);
        }
        if (hasNext) {
            As[nxt][aC4 * 4 + 0][aRow] = av.x;
            As[nxt][aC4 * 4 + 1][aRow] = av.y;
            As[nxt][aC4 * 4 + 2][aRow] = av.z;
            As[nxt][aC4 * 4 + 3][aRow] = av.w;
            *reinterpret_cast<float4*>(&Ws[nxt][wR][wC]) = wv;
        }
        __syncthreads();
    }

#pragma unroll
    for (int i = 0; i < 4; i++) {
        int row = bm + ty * 4 + i;
#pragma unroll
        for (int j = 0; j < 4; j++) {
            int n = bn + tx * 4 + j;
            if (n < N) Cp[(size_t)row * N + n] = acc[i][j];
        }
    }
}

// ---------------------------------------------------------------------------
// Kernel 3: split-K reduce + bias + relu (+ optional transpose, norm extract).
// ---------------------------------------------------------------------------
__global__ __launch_bounds__(256) void reduce_k(
    const float* __restrict__ Cpart, float* __restrict__ C, float* __restrict__ CT,
    const float* __restrict__ bias0, const float* __restrict__ bias1,
    int Mtot, int Mh, int N, int KS, int ldCT, int relu, int writeNorm)
{
    int idx = blockIdx.x * 256 + threadIdx.x;
    int e = idx * 4;
    if (e >= Mtot * N) return;
    int row = e / N;
    int n = e % N;

    float4 acc = make_float4(0.f, 0.f, 0.f, 0.f);
    for (int ks = 0; ks < KS; ks++) {
        float4 v = *reinterpret_cast<const float4*>(&Cpart[((size_t)ks * Mtot + row) * N + n]);
        acc.x += v.x; acc.y += v.y; acc.z += v.z; acc.w += v.w;
    }
    if (bias0) {
        const float* bias = (row < Mh) ? bias0 : bias1;
        float4 bv = *reinterpret_cast<const float4*>(&bias[n]);
        acc.x += bv.x; acc.y += bv.y; acc.z += bv.z; acc.w += bv.w;
    }
    if (relu) {
        acc.x = fmaxf(acc.x, 0.f); acc.y = fmaxf(acc.y, 0.f);
        acc.z = fmaxf(acc.z, 0.f); acc.w = fmaxf(acc.w, 0.f);
    }
    *reinterpret_cast<float4*>(&C[(size_t)row * N + n]) = acc;
    if (CT) {
        CT[(size_t)(n + 0) * ldCT + row] = acc.x;
        CT[(size_t)(n + 1) * ldCT + row] = acc.y;
        CT[(size_t)(n + 2) * ldCT + row] = acc.z;
        CT[(size_t)(n + 3) * ldCT + row] = acc.w;
    }
    if (writeNorm && n <= row && row < n + 4) {
        float d = (row == n) ? acc.x : (row == n + 1) ? acc.y : (row == n + 2) ? acc.z : acc.w;
        g_norm[row] = sqrtf(d);
    }
}

// ---------------------------------------------------------------------------
// Kernel 4: per-row cosine + temperature + logsumexp + positive pair
// ---------------------------------------------------------------------------
__global__ __launch_bounds__(256) void lse_kernel() {
    const int i = blockIdx.x;
    const int t = threadIdx.x;
    __shared__ float red[256];

    const float ni = g_norm[i];
    float l[2];
#pragma unroll
    for (int u = 0; u < 2; u++) {
        int j = t + u * 256;
        float denom = fmaxf(ni * g_norm[j], 1e-8f);
        float c = g_sim[(size_t)i * B_ + j] / denom;
        l[u] = (j == i) ? (-65504.0f / 0.1f) : (c / 0.1f);
    }

    float m = fmaxf(l[0], l[1]);
    red[t] = m;
    __syncthreads();
    for (int s = 128; s > 0; s >>= 1) {
        if (t < s) red[t] = fmaxf(red[t], red[t + s]);
        __syncthreads();
    }
    const float mx = red[0];
    __syncthreads();

    float e = expf(l[0] - mx) + expf(l[1] - mx);
    red[t] = e;
    __syncthreads();
    for (int s = 128; s > 0; s >>= 1) {
        if (t < s) red[t] += red[t + s];
        __syncthreads();
    }

    if (t == 0) {
        float lse = mx + logf(red[0]);
        int pc = (i + MH) & (B_ - 1);
        float denom = fmaxf(ni * g_norm[pc], 1e-8f);
        float pos = (g_sim[(size_t)i * B_ + pc] / denom) / 0.1f;
        g_nll[i] = lse - pos;
    }
}

// ---------------------------------------------------------------------------
// Kernel 5: deterministic mean over 512 nll values -> scalar output
// ---------------------------------------------------------------------------
__global__ void mean_kernel(float* __restrict__ out) {
    __shared__ float red[512];
    int t = threadIdx.x;
    red[t] = g_nll[t];
    __syncthreads();
    for (int s = 256; s > 0; s >>= 1) {
        if (t < s) red[t] += red[t + s];
        __syncthreads();
    }
    if (t == 0) out[0] = red[0] / (float)B_;
}

// ---------------------------------------------------------------------------
extern "C" void kernel_launch(void* const* d_in, const int* in_sizes, int n_in,
                              void* d_out, int out_size) {
    const float* x   = (const float*)d_in[0];
    const float* W1c = (const float*)d_in[1];
    const float* b1c = (const float*)d_in[2];
    const float* W2c = (const float*)d_in[3];
    const float* b2c = (const float*)d_in[4];
    const float* W1a = (const float*)d_in[5];
    const float* b1a = (const float*)d_in[6];
    const float* W2a = (const float*)d_in[7];
    const float* b2a = (const float*)d_in[8];
    float* out = (float*)d_out;

    float *p_pooled, *p_part, *p_h, *p_z, *p_zT, *p_sim;
    cudaGetSymbolAddress((void**)&p_pooled, g_pooled);
    cudaGetSymbolAddress((void**)&p_part, g_part);
    cudaGetSymbolAddress((void**)&p_h, g_h);
    cudaGetSymbolAddress((void**)&p_z, g_z);
    cudaGetSymbolAddress((void**)&p_zT, g_zT);
    cudaGetSymbolAddress((void**)&p_sim, g_sim);

    // 1. mean pooling: 8-way split over S, then reduce
    pool_kernel<<<dim3(B_, SPLIT), 256>>>(x);
    pool_reduce_kernel<<<B_, 256>>>();

    // 2. layer 1: h = relu(pooled @ W1 + b1). M=256x2, K=960 (KS=4, Kc=240), N=480
    gemm_splitk<<<dim3(8, 4, 2 * 4), 256>>>(p_pooled, W1c, W1a, p_part,
                                            MH, D_, H1, 240, 4);
    reduce_k<<<(B_ * H1 / 4 + 255) / 256, 256>>>(p_part, p_h, nullptr, b1c, b1a,
                                                 B_, MH, H1, 4, 0, 1, 0);

    // 3. layer 2: z = h @ W2 + b2 (+ zT). M=256x2, K=480 (KS=5, Kc=96), N=240
    gemm_splitk<<<dim3(4, 4, 2 * 5), 256>>>(p_h, W2c, W2a, p_part,
                                            MH, H1, H2, 96, 5);
    reduce_k<<<(B_ * H2 / 4 + 255) / 256, 256>>>(p_part, p_z, p_zT, b2c, b2a,
                                                 B_, MH, H2, 5, B_, 0, 0);

    // 4. sim = z @ zT. M=512, K=240 (KS=3, Kc=80), N=512. Norms folded in.
    gemm_splitk<<<dim3(8, 8, 1 * 3), 256>>>(p_z, p_zT, p_zT, p_part,
                                            B_, H2, B_, 80, 3);
    reduce_k<<<(B_ * B_ / 4 + 255) / 256, 256>>>(p_part, p_sim, nullptr, nullptr, nullptr,
                                                 B_, B_, B_, 3, 0, 0, 1);

    // 5-6. epilogue
    lse_kernel<<<B_, 256>>>();
    mean_kernel<<<1, B_>>>(out);
}

// round 5
// speedup vs baseline: 1.3872x; 1.0021x over previous
#include <cuda_runtime.h>
#include <cuda_bf16.h>
#include <math.h>

// Problem constants
#define B_   512
#define S_   512
#define D_   960
#define H1   480   // D/2
#define H2   240   // D/4
#define MH   256   // B/2
#define D4   240   // D/4 float4s per row
#define SPLIT 8
#define SCHUNK (S_ / SPLIT)   // 64
#define NSLOT (SPLIT * 2)     // 16 pooling partial slots

// Scratch (device globals; no allocations allowed)
__device__ __align__(16) float g_pp[NSLOT * B_ * D_];   // pooling partials (31MB)
__device__ __align__(16) float g_pooled[B_ * D_];       // [512,960]
__device__ __align__(16) float g_part1[4 * B_ * H1];    // L1 partials / sim partials (reused)
__device__ __align__(16) float g_part2[5 * B_ * H2];    // L2 partials
__device__ __align__(16) float g_z[B_ * H2];            // [512,240]
__device__ __align__(16) float g_zT[H2 * B_];           // [240,512]
__device__ __align__(16) float g_sim[B_ * B_];          // [512,512]
__device__ __align__(16) float g_norm[B_];
__device__ __align__(16) float g_nll[B_];

// ---------------------------------------------------------------------------
// Kernel 1a: partial mean-pool. Grid (SPLIT, B) — chunk-major so one resident
// wave clusters on few distinct x regions (TLB/L2 page locality).
// 480 threads: lanes 0..239 handle even s-rows, 240..479 odd. 16 partial slots.
// ---------------------------------------------------------------------------
__global__ __launch_bounds__(480) void pool_kernel(const float* __restrict__ x) {
    const int c = blockIdx.x;          // chunk (fastest)
    const int b = blockIdx.y;          // batch row
    const int t = threadIdx.x;         // 0..479
    const int sOff = (t >= D4) ? 1 : 0;
    const int col = t - sOff * D4;     // 0..239

    const float4* xb = reinterpret_cast<const float4*>(x)
                     + ((size_t)b * S_ + (size_t)c * SCHUNK + sOff) * D4 + col;
    float4 a0 = make_float4(0.f, 0.f, 0.f, 0.f);
    float4 a1 = make_float4(0.f, 0.f, 0.f, 0.f);
    // 32 rows per thread (stride 2), unroll 8 -> deep MLP
#pragma unroll 8
    for (int i = 0; i < SCHUNK / 2; i++) {
        float4 v = __ldcs(&xb[(size_t)(i * 2) * D4]);
        if (i & 1) { a1.x += v.x; a1.y += v.y; a1.z += v.z; a1.w += v.w; }
        else       { a0.x += v.x; a0.y += v.y; a0.z += v.z; a0.w += v.w; }
    }
    float4 r = make_float4(a0.x + a1.x, a0.y + a1.y, a0.z + a1.z, a0.w + a1.w);
    const int slot = c * 2 + sOff;
    reinterpret_cast<float4*>(g_pp)[((size_t)slot * B_ + b) * D4 + col] = r;
}

// ---------------------------------------------------------------------------
// Kernel 1b: reduce the NSLOT partials, scale by 1/S.
// ---------------------------------------------------------------------------
__global__ __launch_bounds__(256) void pool_reduce_kernel() {
    const int b = blockIdx.x;
    const int t = threadIdx.x;
    if (t >= D4) return;
    const float4* pp = reinterpret_cast<const float4*>(g_pp);
    float4 acc = make_float4(0.f, 0.f, 0.f, 0.f);
#pragma unroll
    for (int c = 0; c < NSLOT; c++) {
        float4 v = pp[((size_t)c * B_ + b) * D4 + t];
        acc.x += v.x; acc.y += v.y; acc.z += v.z; acc.w += v.w;
    }
    const float inv = 1.0f / (float)S_;
    float4 r = make_float4(acc.x * inv, acc.y * inv, acc.z * inv, acc.w * inv);
    reinterpret_cast<float4*>(g_pooled)[(size_t)b * D4 + t] = r;
}

// ---------------------------------------------------------------------------
// Kernel 2: split-K tiled fp32 GEMM partials (plain A operand).
//   64x64 tile, BK=16, 256 threads, 4x4 microtile, double-buffered smem.
// ---------------------------------------------------------------------------
#define BM 64
#define BN 64
#define BK 16
#define AP 68

__global__ __launch_bounds__(256) void gemm_splitk(
    const float* __restrict__ Abase,
    const float* __restrict__ W0, const float* __restrict__ W1,
    float* __restrict__ Cpart,
    int Mh, int Ktot, int N, int Kc, int KS)
{
    __shared__ float As[2][BK][AP];
    __shared__ float Ws[2][BK][BN];

    const int half = blockIdx.z / KS;
    const int ks   = blockIdx.z % KS;
    const int halves = gridDim.z / KS;
    const int Mtot = halves * Mh;
    const float* A = Abase + (size_t)half * Mh * Ktot + (size_t)ks * Kc;
    const float* W = (half ? W1 : W0) + (size_t)ks * Kc * N;
    float* Cp = Cpart + ((size_t)ks * Mtot + (size_t)half * Mh) * N;

    const int tid = threadIdx.x;
    const int tx = tid & 15;
    const int ty = tid >> 4;
    const int bm = blockIdx.y * BM;
    const int bn = blockIdx.x * BN;

    const int aRow = tid >> 2;
    const int aC4  = tid & 3;
    const int wR   = tid >> 4;
    const int wC   = (tid & 15) * 4;

    float acc[4][4];
#pragma unroll
    for (int i = 0; i < 4; i++)
#pragma unroll
        for (int j = 0; j < 4; j++) acc[i][j] = 0.f;

    const bool wOk = (bn + wC) < N;

    float4 av = *reinterpret_cast<const float4*>(&A[(size_t)(bm + aRow) * Ktot + aC4 * 4]);
    float4 wv = make_float4(0.f, 0.f, 0.f, 0.f);
    if (wOk) wv = *reinterpret_cast<const float4*>(&W[(size_t)wR * N + bn + wC]);
    As[0][aC4 * 4 + 0][aRow] = av.x;
    As[0][aC4 * 4 + 1][aRow] = av.y;
    As[0][aC4 * 4 + 2][aRow] = av.z;
    As[0][aC4 * 4 + 3][aRow] = av.w;
    *reinterpret_cast<float4*>(&Ws[0][wR][wC]) = wv;
    __syncthreads();

    const int nk = Kc / BK;
    for (int t = 0; t < nk; t++) {
        const int cur = t & 1, nxt = cur ^ 1;
        const bool hasNext = (t + 1) < nk;
        if (hasNext) {
            const int k0 = (t + 1) * BK;
            av = *reinterpret_cast<const float4*>(&A[(size_t)(bm + aRow) * Ktot + k0 + aC4 * 4]);
            wv = make_float4(0.f, 0.f, 0.f, 0.f);
            if (wOk) wv = *reinterpret_cast<const float4*>(&W[(size_t)(k0 + wR) * N + bn + wC]);
        }
#pragma unroll
        for (int kk = 0; kk < BK; kk++) {
            float4 a = *reinterpret_cast<const float4*>(&As[cur][kk][ty * 4]);
            float4 b = *reinterpret_cast<const float4*>(&Ws[cur][kk][tx * 4]);
            float ar[4] = {a.x, a.y, a.z, a.w};
            float br[4] = {b.x, b.y, b.z, b.w};
#pragma unroll
            for (int i = 0; i < 4; i++)
#pragma unroll
                for (int j = 0; j < 4; j++)
                    acc[i][j] = fmaf(ar[i], br[j], acc[i][j]);
        }
        if (hasNext) {
            As[nxt][aC4 * 4 + 0][aRow] = av.x;
            As[nxt][aC4 * 4 + 1][aRow] = av.y;
            As[nxt][aC4 * 4 + 2][aRow] = av.z;
            As[nxt][aC4 * 4 + 3][aRow] = av.w;
            *reinterpret_cast<float4*>(&Ws[nxt][wR][wC]) = wv;
        }
        __syncthreads();
    }

#pragma unroll
    for (int i = 0; i < 4; i++) {
        int row = bm + ty * 4 + i;
#pragma unroll
        for (int j = 0; j < 4; j++) {
            int n = bn + tx * 4 + j;
            if (n < N) Cp[(size_t)row * N + n] = acc[i][j];
        }
    }
}

// ---------------------------------------------------------------------------
// Kernel 2b: layer-2 GEMM with FUSED layer-1 reduce+bias+relu on the A side.
//   A element h[rowg][k] = relu(sum_{p<4} part1[p][rowg][k] + b1[k]).
//   Otherwise identical split-K structure. Writes L2 partials.
// ---------------------------------------------------------------------------
__global__ __launch_bounds__(256) void gemm_l2_fused(
    const float* __restrict__ P1,                  // layer-1 partials [4][512][H1]
    const float* __restrict__ W0, const float* __restrict__ W1,
    const float* __restrict__ bias10, const float* __restrict__ bias11,
    float* __restrict__ Cpart,
    int Mh, int N, int Kc, int KS)
{
    __shared__ float As[2][BK][AP];
    __shared__ float Ws[2][BK][BN];

    const int half = blockIdx.z / KS;
    const int ks   = blockIdx.z % KS;
    const float* W = (half ? W1 : W0) + (size_t)ks * Kc * N;
    const float* b1 = half ? bias11 : bias10;
    float* Cp = Cpart + ((size_t)ks * B_ + (size_t)half * Mh) * N;

    const int tid = threadIdx.x;
    const int tx = tid & 15;
    const int ty = tid >> 4;
    const int bm = blockIdx.y * BM;
    const int bn = blockIdx.x * BN;

    const int aRow = tid >> 2;
    const int aC4  = tid & 3;
    const int wR   = tid >> 4;
    const int wC   = (tid & 15) * 4;

    const int rowg = half * Mh + bm + aRow;        // global h row for this thread's A loads
    const int kbase = ks * Kc + aC4 * 4;           // global h column base

    float acc[4][4];
#pragma unroll
    for (int i = 0; i < 4; i++)
#pragma unroll
        for (int j = 0; j < 4; j++) acc[i][j] = 0.f;

    const bool wOk = (bn + wC) < N;

    // fused A load: relu(sum of 4 partials + bias)
    auto loadA = [&](int k0) -> float4 {
        const size_t base = (size_t)rowg * H1 + kbase + k0;
        float4 s = *reinterpret_cast<const float4*>(&P1[base]);
#pragma unroll
        for (int p = 1; p < 4; p++) {
            float4 v = *reinterpret_cast<const float4*>(&P1[(size_t)p * B_ * H1 + base]);
            s.x += v.x; s.y += v.y; s.z += v.z; s.w += v.w;
        }
        float4 bv = *reinterpret_cast<const float4*>(&b1[kbase + k0]);
        s.x = fmaxf(s.x + bv.x, 0.f); s.y = fmaxf(s.y + bv.y, 0.f);
        s.z = fmaxf(s.z + bv.z, 0.f); s.w = fmaxf(s.w + bv.w, 0.f);
        return s;
    };

    float4 av = loadA(0);
    float4 wv = make_float4(0.f, 0.f, 0.f, 0.f);
    if (wOk) wv = *reinterpret_cast<const float4*>(&W[(size_t)wR * N + bn + wC]);
    As[0][aC4 * 4 + 0][aRow] = av.x;
    As[0][aC4 * 4 + 1][aRow] = av.y;
    As[0][aC4 * 4 + 2][aRow] = av.z;
    As[0][aC4 * 4 + 3][aRow] = av.w;
    *reinterpret_cast<float4*>(&Ws[0][wR][wC]) = wv;
    __syncthreads();

    const int nk = Kc / BK;
    for (int t = 0; t < nk; t++) {
        const int cur = t & 1, nxt = cur ^ 1;
        const bool hasNext = (t + 1) < nk;
        if (hasNext) {
            const int k0 = (t + 1) * BK;
            av = loadA(k0);
            wv = make_float4(0.f, 0.f, 0.f, 0.f);
            if (wOk) wv = *reinterpret_cast<const float4*>(&W[(size_t)(k0 + wR) * N + bn + wC]);
        }
#pragma unroll
        for (int kk = 0; kk < BK; kk++) {
            float4 a = *reinterpret_cast<const float4*>(&As[cur][kk][ty * 4]);
            float4 b = *reinterpret_cast<const float4*>(&Ws[cur][kk][tx * 4]);
            float ar[4] = {a.x, a.y, a.z, a.w};
            float br[4] = {b.x, b.y, b.z, b.w};
#pragma unroll
            for (int i = 0; i < 4; i++)
#pragma unroll
                for (int j = 0; j < 4; j++)
                    acc[i][j] = fmaf(ar[i], br[j], acc[i][j]);
        }
        if (hasNext) {
            As[nxt][aC4 * 4 + 0][aRow] = av.x;
            As[nxt][aC4 * 4 + 1][aRow] = av.y;
            As[nxt][aC4 * 4 + 2][aRow] = av.z;
            As[nxt][aC4 * 4 + 3][aRow] = av.w;
            *reinterpret_cast<float4*>(&Ws[nxt][wR][wC]) = wv;
        }
        __syncthreads();
    }

#pragma unroll
    for (int i = 0; i < 4; i++) {
        int row = bm + ty * 4 + i;
#pragma unroll
        for (int j = 0; j < 4; j++) {
            int n = bn + tx * 4 + j;
            if (n < N) Cp[(size_t)row * N + n] = acc[i][j];
        }
    }
}

// ---------------------------------------------------------------------------
// Kernel 3: split-K reduce + bias (+ optional transpose, norm extract).
// ---------------------------------------------------------------------------
__global__ __launch_bounds__(256) void reduce_k(
    const float* __restrict__ Cpart, float* __restrict__ C, float* __restrict__ CT,
    const float* __restrict__ bias0, const float* __restrict__ bias1,
    int Mtot, int Mh, int N, int KS, int ldCT, int relu, int writeNorm)
{
    int idx = blockIdx.x * 256 + threadIdx.x;
    int e = idx * 4;
    if (e >= Mtot * N) return;
    int row = e / N;
    int n = e % N;

    float4 acc = make_float4(0.f, 0.f, 0.f, 0.f);
    for (int ks = 0; ks < KS; ks++) {
        float4 v = *reinterpret_cast<const float4*>(&Cpart[((size_t)ks * Mtot + row) * N + n]);
        acc.x += v.x; acc.y += v.y; acc.z += v.z; acc.w += v.w;
    }
    if (bias0) {
        const float* bias = (row < Mh) ? bias0 : bias1;
        float4 bv = *reinterpret_cast<const float4*>(&bias[n]);
        acc.x += bv.x; acc.y += bv.y; acc.z += bv.z; acc.w += bv.w;
    }
    if (relu) {
        acc.x = fmaxf(acc.x, 0.f); acc.y = fmaxf(acc.y, 0.f);
        acc.z = fmaxf(acc.z, 0.f); acc.w = fmaxf(acc.w, 0.f);
    }
    *reinterpret_cast<float4*>(&C[(size_t)row * N + n]) = acc;
    if (CT) {
        CT[(size_t)(n + 0) * ldCT + row] = acc.x;
        CT[(size_t)(n + 1) * ldCT + row] = acc.y;
        CT[(size_t)(n + 2) * ldCT + row] = acc.z;
        CT[(size_t)(n + 3) * ldCT + row] = acc.w;
    }
    if (writeNorm && n <= row && row < n + 4) {
        float d = (row == n) ? acc.x : (row == n + 1) ? acc.y : (row == n + 2) ? acc.z : acc.w;
        g_norm[row] = sqrtf(d);
    }
}

// ---------------------------------------------------------------------------
// Kernel 4: per-row cosine + temperature + logsumexp + positive pair
// ---------------------------------------------------------------------------
__global__ __launch_bounds__(256) void lse_kernel() {
    const int i = blockIdx.x;
    const int t = threadIdx.x;
    __shared__ float red[256];

    const float ni = g_norm[i];
    float l[2];
#pragma unroll
    for (int u = 0; u < 2; u++) {
        int j = t + u * 256;
        float denom = fmaxf(ni * g_norm[j], 1e-8f);
        float c = g_sim[(size_t)i * B_ + j] / denom;
        l[u] = (j == i) ? (-65504.0f / 0.1f) : (c / 0.1f);
    }

    float m = fmaxf(l[0], l[1]);
    red[t] = m;
    __syncthreads();
    for (int s = 128; s > 0; s >>= 1) {
        if (t < s) red[t] = fmaxf(red[t], red[t + s]);
        __syncthreads();
    }
    const float mx = red[0];
    __syncthreads();

    float e = expf(l[0] - mx) + expf(l[1] - mx);
    red[t] = e;
    __syncthreads();
    for (int s = 128; s > 0; s >>= 1) {
        if (t < s) red[t] += red[t + s];
        __syncthreads();
    }

    if (t == 0) {
        float lse = mx + logf(red[0]);
        int pc = (i + MH) & (B_ - 1);
        float denom = fmaxf(ni * g_norm[pc], 1e-8f);
        float pos = (g_sim[(size_t)i * B_ + pc] / denom) / 0.1f;
        g_nll[i] = lse - pos;
    }
}

// ---------------------------------------------------------------------------
// Kernel 5: deterministic mean over 512 nll values -> scalar output
// ---------------------------------------------------------------------------
__global__ void mean_kernel(float* __restrict__ out) {
    __shared__ float red[512];
    int t = threadIdx.x;
    red[t] = g_nll[t];
    __syncthreads();
    for (int s = 256; s > 0; s >>= 1) {
        if (t < s) red[t] += red[t + s];
        __syncthreads();
    }
    if (t == 0) out[0] = red[0] / (float)B_;
}

// ---------------------------------------------------------------------------
extern "C" void kernel_launch(void* const* d_in, const int* in_sizes, int n_in,
                              void* d_out, int out_size) {
    const float* x   = (const float*)d_in[0];
    const float* W1c = (const float*)d_in[1];
    const float* b1c = (const float*)d_in[2];
    const float* W2c = (const float*)d_in[3];
    const float* b2c = (const float*)d_in[4];
    const float* W1a = (const float*)d_in[5];
    const float* b1a = (const float*)d_in[6];
    const float* W2a = (const float*)d_in[7];
    const float* b2a = (const float*)d_in[8];
    float* out = (float*)d_out;

    float *p_pooled, *p_part1, *p_part2, *p_z, *p_zT, *p_sim;
    cudaGetSymbolAddress((void**)&p_pooled, g_pooled);
    cudaGetSymbolAddress((void**)&p_part1, g_part1);
    cudaGetSymbolAddress((void**)&p_part2, g_part2);
    cudaGetSymbolAddress((void**)&p_z, g_z);
    cudaGetSymbolAddress((void**)&p_zT, g_zT);
    cudaGetSymbolAddress((void**)&p_sim, g_sim);

    // 0-1. mean pooling (chunk-major grid), then reduce
    pool_kernel<<<dim3(SPLIT, B_), 480>>>(x);
    pool_reduce_kernel<<<B_, 256>>>();

    // 2. layer 1 partials: pooled @ W1. K=960 (KS=4, Kc=240), N=480
    gemm_splitk<<<dim3(8, 4, 2 * 4), 256>>>(p_pooled, W1c, W1a, p_part1,
                                            MH, D_, H1, 240, 4);

    // 3. layer 2 with fused L1 reduce+bias+relu on the A side.
    //    K=480 (KS=5, Kc=96), N=240 -> L2 partials
    gemm_l2_fused<<<dim3(4, 4, 2 * 5), 256>>>(p_part1, W2c, W2a, b1c, b1a,
                                              p_part2, MH, H2, 96, 5);

    // 4. reduce L2 partials -> z (+ bias b2) and zT
    reduce_k<<<(B_ * H2 / 4 + 255) / 256, 256>>>(p_part2, p_z, p_zT, b2c, b2a,
                                                 B_, MH, H2, 5, B_, 0, 0);

    // 5. sim = z @ zT. K=240 (KS=3, Kc=80), N=512. (launch #6 -> profiled)
    gemm_splitk<<<dim3(8, 8, 1 * 3), 256>>>(p_z, p_zT, p_zT, p_part1,
                                            B_, H2, B_, 80, 3);

    // 6. reduce sim partials; norms folded in
    reduce_k<<<(B_ * B_ / 4 + 255) / 256, 256>>>(p_part1, p_sim, nullptr, nullptr, nullptr,
                                                 B_, B_, B_, 3, 0, 0, 1);

    // 7-8. epilogue
    lse_kernel<<<B_, 256>>>();
    mean_kernel<<<1, B_>>>(out);
}

// round 6
// speedup vs baseline: 1.4734x; 1.0622x over previous
#include <cuda_runtime.h>
#include <cuda_bf16.h>
#include <math.h>

// Problem constants
#define B_   512
#define S_   512
#define D_   960
#define H1   480   // D/2
#define H2   240   // D/4
#define MH   256   // B/2
#define D4   240   // D/4 float4s per row
#define SPLIT 8
#define SCHUNK (S_ / SPLIT)   // 64
#define NSLOT SPLIT           // 8 pooling partial slots (even/odd merged in smem)

// Scratch (device globals; no allocations allowed)
__device__ __align__(16) float g_pp[NSLOT * B_ * D_];   // pooling partials (15.7MB)
__device__ __align__(16) float g_pooled[B_ * D_];       // [512,960]
__device__ __align__(16) float g_part1[4 * B_ * H1];    // L1 partials / sim partials (reused)
__device__ __align__(16) float g_part2[5 * B_ * H2];    // L2 partials
__device__ __align__(16) float g_z[B_ * H2];            // [512,240]
__device__ __align__(16) float g_zT[H2 * B_];           // [240,512]
__device__ __align__(16) float g_norm[B_];
__device__ __align__(16) float g_nll[B_];

// ---------------------------------------------------------------------------
// f32x2 helpers
// ---------------------------------------------------------------------------
__device__ __forceinline__ void ffma2(unsigned long long& d,
                                      unsigned long long a, unsigned long long b) {
    asm("fma.rn.f32x2 %0, %1, %2, %0;" : "+l"(d) : "l"(a), "l"(b));
}
__device__ __forceinline__ unsigned long long bcast2(float v) {
    unsigned long long r;
    asm("mov.b64 %0, {%1, %1};" : "=l"(r) : "r"(__float_as_uint(v)));
    return r;
}
__device__ __forceinline__ float2 unpk(unsigned long long v) {
    float2 f;
    asm("mov.b64 {%0, %1}, %2;" : "=f"(f.x), "=f"(f.y) : "l"(v));
    return f;
}

// ---------------------------------------------------------------------------
// Kernel 1a: partial mean-pool. Grid (SPLIT, B). 480 threads: lanes 0..239
// even s-rows, 240..479 odd; halves merged in smem -> one slot per chunk.
// ---------------------------------------------------------------------------
__global__ __launch_bounds__(480) void pool_kernel(const float* __restrict__ x) {
    __shared__ float4 mrg[D4];
    const int c = blockIdx.x;
    const int b = blockIdx.y;
    const int t = threadIdx.x;
    const int sOff = (t >= D4) ? 1 : 0;
    const int col = t - sOff * D4;

    const float4* xb = reinterpret_cast<const float4*>(x)
                     + ((size_t)b * S_ + (size_t)c * SCHUNK + sOff) * D4 + col;
    float4 a0 = make_float4(0.f, 0.f, 0.f, 0.f);
    float4 a1 = make_float4(0.f, 0.f, 0.f, 0.f);
#pragma unroll 8
    for (int i = 0; i < SCHUNK / 2; i++) {
        float4 v = __ldcs(&xb[(size_t)(i * 2) * D4]);
        if (i & 1) { a1.x += v.x; a1.y += v.y; a1.z += v.z; a1.w += v.w; }
        else       { a0.x += v.x; a0.y += v.y; a0.z += v.z; a0.w += v.w; }
    }
    float4 r = make_float4(a0.x + a1.x, a0.y + a1.y, a0.z + a1.z, a0.w + a1.w);
    if (sOff == 1) mrg[col] = r;
    __syncthreads();
    if (sOff == 0) {
        float4 m = mrg[col];
        r.x += m.x; r.y += m.y; r.z += m.z; r.w += m.w;
        reinterpret_cast<float4*>(g_pp)[((size_t)c * B_ + b) * D4 + col] = r;
    }
}

// ---------------------------------------------------------------------------
// Kernel 1b: reduce the NSLOT partials, scale by 1/S.
// ---------------------------------------------------------------------------
__global__ __launch_bounds__(256) void pool_reduce_kernel() {
    const int b = blockIdx.x;
    const int t = threadIdx.x;
    if (t >= D4) return;
    const float4* pp = reinterpret_cast<const float4*>(g_pp);
    float4 acc = make_float4(0.f, 0.f, 0.f, 0.f);
#pragma unroll
    for (int c = 0; c < NSLOT; c++) {
        float4 v = pp[((size_t)c * B_ + b) * D4 + t];
        acc.x += v.x; acc.y += v.y; acc.z += v.z; acc.w += v.w;
    }
    const float inv = 1.0f / (float)S_;
    float4 r = make_float4(acc.x * inv, acc.y * inv, acc.z * inv, acc.w * inv);
    reinterpret_cast<float4*>(g_pooled)[(size_t)b * D4 + t] = r;
}

// ---------------------------------------------------------------------------
// GEMM tiles: 32x64, BK=16, 128 threads, 4x4 microtile (f32x2 pairs),
// double-buffered. Many blocks per SM for latency hiding.
// ---------------------------------------------------------------------------
#define BM 32
#define BN 64
#define BK 16
#define AP 36   // padded A pitch

// Kernel 2: plain split-K GEMM partials. blockIdx.z = half*KS + ks.
__global__ __launch_bounds__(128) void gemm_splitk(
    const float* __restrict__ Abase,
    const float* __restrict__ W0, const float* __restrict__ W1,
    float* __restrict__ Cpart,
    int Mh, int Ktot, int N, int Kc, int KS)
{
    __shared__ float As[2][BK][AP];
    __shared__ float Ws[2][BK][BN];

    const int half = blockIdx.z / KS;
    const int ks   = blockIdx.z % KS;
    const int halves = gridDim.z / KS;
    const int Mtot = halves * Mh;
    const float* A = Abase + (size_t)half * Mh * Ktot + (size_t)ks * Kc;
    const float* W = (half ? W1 : W0) + (size_t)ks * Kc * N;
    float* Cp = Cpart + ((size_t)ks * Mtot + (size_t)half * Mh) * N;

    const int tid = threadIdx.x;       // 128
    const int tx = tid & 15;           // 16 col-groups of 4
    const int ty = tid >> 4;           // 8 row-groups of 4
    const int bm = blockIdx.y * BM;
    const int bn = blockIdx.x * BN;

    const int aRow = tid >> 2;         // 0..31
    const int aC4  = tid & 3;
    const int wR   = tid >> 4;         // 0..7 (and +8)
    const int wC   = (tid & 15) * 4;

    unsigned long long acc[4][2];
#pragma unroll
    for (int i = 0; i < 4; i++) { acc[i][0] = 0ull; acc[i][1] = 0ull; }

    const bool wOk = (bn + wC) < N;

    float4 av = *reinterpret_cast<const float4*>(&A[(size_t)(bm + aRow) * Ktot + aC4 * 4]);
    float4 wv0 = make_float4(0.f, 0.f, 0.f, 0.f), wv1 = wv0;
    if (wOk) {
        wv0 = *reinterpret_cast<const float4*>(&W[(size_t)wR * N + bn + wC]);
        wv1 = *reinterpret_cast<const float4*>(&W[(size_t)(wR + 8) * N + bn + wC]);
    }
    As[0][aC4 * 4 + 0][aRow] = av.x;
    As[0][aC4 * 4 + 1][aRow] = av.y;
    As[0][aC4 * 4 + 2][aRow] = av.z;
    As[0][aC4 * 4 + 3][aRow] = av.w;
    *reinterpret_cast<float4*>(&Ws[0][wR][wC])     = wv0;
    *reinterpret_cast<float4*>(&Ws[0][wR + 8][wC]) = wv1;
    __syncthreads();

    const int nk = Kc / BK;
    for (int t = 0; t < nk; t++) {
        const int cur = t & 1, nxt = cur ^ 1;
        const bool hasNext = (t + 1) < nk;
        if (hasNext) {
            const int k0 = (t + 1) * BK;
            av = *reinterpret_cast<const float4*>(&A[(size_t)(bm + aRow) * Ktot + k0 + aC4 * 4]);
            wv0 = make_float4(0.f, 0.f, 0.f, 0.f); wv1 = wv0;
            if (wOk) {
                wv0 = *reinterpret_cast<const float4*>(&W[(size_t)(k0 + wR) * N + bn + wC]);
                wv1 = *reinterpret_cast<const float4*>(&W[(size_t)(k0 + wR + 8) * N + bn + wC]);
            }
        }
#pragma unroll
        for (int kk = 0; kk < BK; kk++) {
            float4 a = *reinterpret_cast<const float4*>(&As[cur][kk][ty * 4]);
            ulonglong2 b = *reinterpret_cast<const ulonglong2*>(&Ws[cur][kk][tx * 4]);
            unsigned long long aa;
            aa = bcast2(a.x); ffma2(acc[0][0], aa, b.x); ffma2(acc[0][1], aa, b.y);
            aa = bcast2(a.y); ffma2(acc[1][0], aa, b.x); ffma2(acc[1][1], aa, b.y);
            aa = bcast2(a.z); ffma2(acc[2][0], aa, b.x); ffma2(acc[2][1], aa, b.y);
            aa = bcast2(a.w); ffma2(acc[3][0], aa, b.x); ffma2(acc[3][1], aa, b.y);
        }
        if (hasNext) {
            As[nxt][aC4 * 4 + 0][aRow] = av.x;
            As[nxt][aC4 * 4 + 1][aRow] = av.y;
            As[nxt][aC4 * 4 + 2][aRow] = av.z;
            As[nxt][aC4 * 4 + 3][aRow] = av.w;
            *reinterpret_cast<float4*>(&Ws[nxt][wR][wC])     = wv0;
            *reinterpret_cast<float4*>(&Ws[nxt][wR + 8][wC]) = wv1;
        }
        __syncthreads();
    }

#pragma unroll
    for (int i = 0; i < 4; i++) {
        int row = bm + ty * 4 + i;
#pragma unroll
        for (int jp = 0; jp < 2; jp++) {
            float2 c = unpk(acc[i][jp]);
            int n = bn + tx * 4 + jp * 2;
            if (n + 1 < N) {
                Cp[(size_t)row * N + n]     = c.x;
                Cp[(size_t)row * N + n + 1] = c.y;
            }
        }
    }
}

// Kernel 2b: layer-2 GEMM with fused layer-1 reduce+bias+relu on the A side.
__global__ __launch_bounds__(128) void gemm_l2_fused(
    const float* __restrict__ P1,
    const float* __restrict__ W0, const float* __restrict__ W1,
    const float* __restrict__ bias10, const float* __restrict__ bias11,
    float* __restrict__ Cpart,
    int Mh, int N, int Kc, int KS)
{
    __shared__ float As[2][BK][AP];
    __shared__ float Ws[2][BK][BN];

    const int half = blockIdx.z / KS;
    const int ks   = blockIdx.z % KS;
    const float* W = (half ? W1 : W0) + (size_t)ks * Kc * N;
    const float* b1 = half ? bias11 : bias10;
    float* Cp = Cpart + ((size_t)ks * B_ + (size_t)half * Mh) * N;

    const int tid = threadIdx.x;
    const int tx = tid & 15;
    const int ty = tid >> 4;
    const int bm = blockIdx.y * BM;
    const int bn = blockIdx.x * BN;

    const int aRow = tid >> 2;
    const int aC4  = tid & 3;
    const int wR   = tid >> 4;
    const int wC   = (tid & 15) * 4;

    const int rowg = half * Mh + bm + aRow;
    const int kbase = ks * Kc + aC4 * 4;

    unsigned long long acc[4][2];
#pragma unroll
    for (int i = 0; i < 4; i++) { acc[i][0] = 0ull; acc[i][1] = 0ull; }

    const bool wOk = (bn + wC) < N;

    auto loadA = [&](int k0) -> float4 {
        const size_t base = (size_t)rowg * H1 + kbase + k0;
        float4 s = *reinterpret_cast<const float4*>(&P1[base]);
#pragma unroll
        for (int p = 1; p < 4; p++) {
            float4 v = *reinterpret_cast<const float4*>(&P1[(size_t)p * B_ * H1 + base]);
            s.x += v.x; s.y += v.y; s.z += v.z; s.w += v.w;
        }
        float4 bv = *reinterpret_cast<const float4*>(&b1[kbase + k0]);
        s.x = fmaxf(s.x + bv.x, 0.f); s.y = fmaxf(s.y + bv.y, 0.f);
        s.z = fmaxf(s.z + bv.z, 0.f); s.w = fmaxf(s.w + bv.w, 0.f);
        return s;
    };

    float4 av = loadA(0);
    float4 wv0 = make_float4(0.f, 0.f, 0.f, 0.f), wv1 = wv0;
    if (wOk) {
        wv0 = *reinterpret_cast<const float4*>(&W[(size_t)wR * N + bn + wC]);
        wv1 = *reinterpret_cast<const float4*>(&W[(size_t)(wR + 8) * N + bn + wC]);
    }
    As[0][aC4 * 4 + 0][aRow] = av.x;
    As[0][aC4 * 4 + 1][aRow] = av.y;
    As[0][aC4 * 4 + 2][aRow] = av.z;
    As[0][aC4 * 4 + 3][aRow] = av.w;
    *reinterpret_cast<float4*>(&Ws[0][wR][wC])     = wv0;
    *reinterpret_cast<float4*>(&Ws[0][wR + 8][wC]) = wv1;
    __syncthreads();

    const int nk = Kc / BK;
    for (int t = 0; t < nk; t++) {
        const int cur = t & 1, nxt = cur ^ 1;
        const bool hasNext = (t + 1) < nk;
        if (hasNext) {
            const int k0 = (t + 1) * BK;
            av = loadA(k0);
            wv0 = make_float4(0.f, 0.f, 0.f, 0.f); wv1 = wv0;
            if (wOk) {
                wv0 = *reinterpret_cast<const float4*>(&W[(size_t)(k0 + wR) * N + bn + wC]);
                wv1 = *reinterpret_cast<const float4*>(&W[(size_t)(k0 + wR + 8) * N + bn + wC]);
            }
        }
#pragma unroll
        for (int kk = 0; kk < BK; kk++) {
            float4 a = *reinterpret_cast<const float4*>(&As[cur][kk][ty * 4]);
            ulonglong2 b = *reinterpret_cast<const ulonglong2*>(&Ws[cur][kk][tx * 4]);
            unsigned long long aa;
            aa = bcast2(a.x); ffma2(acc[0][0], aa, b.x); ffma2(acc[0][1], aa, b.y);
            aa = bcast2(a.y); ffma2(acc[1][0], aa, b.x); ffma2(acc[1][1], aa, b.y);
            aa = bcast2(a.z); ffma2(acc[2][0], aa, b.x); ffma2(acc[2][1], aa, b.y);
            aa = bcast2(a.w); ffma2(acc[3][0], aa, b.x); ffma2(acc[3][1], aa, b.y);
        }
        if (hasNext) {
            As[nxt][aC4 * 4 + 0][aRow] = av.x;
            As[nxt][aC4 * 4 + 1][aRow] = av.y;
            As[nxt][aC4 * 4 + 2][aRow] = av.z;
            As[nxt][aC4 * 4 + 3][aRow] = av.w;
            *reinterpret_cast<float4*>(&Ws[nxt][wR][wC])     = wv0;
            *reinterpret_cast<float4*>(&Ws[nxt][wR + 8][wC]) = wv1;
        }
        __syncthreads();
    }

#pragma unroll
    for (int i = 0; i < 4; i++) {
        int row = bm + ty * 4 + i;
#pragma unroll
        for (int jp = 0; jp < 2; jp++) {
            float2 c = unpk(acc[i][jp]);
            int n = bn + tx * 4 + jp * 2;
            if (n + 1 < N) {
                Cp[(size_t)row * N + n]     = c.x;
                Cp[(size_t)row * N + n + 1] = c.y;
            }
        }
    }
}

// ---------------------------------------------------------------------------
// Kernel 3: split-K reduce + bias + transpose (L2 -> z, zT).
// ---------------------------------------------------------------------------
__global__ __launch_bounds__(256) void reduce_k(
    const float* __restrict__ Cpart, float* __restrict__ C, float* __restrict__ CT,
    const float* __restrict__ bias0, const float* __restrict__ bias1,
    int Mtot, int Mh, int N, int KS, int ldCT)
{
    int idx = blockIdx.x * 256 + threadIdx.x;
    int e = idx * 4;
    if (e >= Mtot * N) return;
    int row = e / N;
    int n = e % N;

    float4 acc = make_float4(0.f, 0.f, 0.f, 0.f);
    for (int ks = 0; ks < KS; ks++) {
        float4 v = *reinterpret_cast<const float4*>(&Cpart[((size_t)ks * Mtot + row) * N + n]);
        acc.x += v.x; acc.y += v.y; acc.z += v.z; acc.w += v.w;
    }
    const float* bias = (row < Mh) ? bias0 : bias1;
    float4 bv = *reinterpret_cast<const float4*>(&bias[n]);
    acc.x += bv.x; acc.y += bv.y; acc.z += bv.z; acc.w += bv.w;
    *reinterpret_cast<float4*>(&C[(size_t)row * N + n]) = acc;
    CT[(size_t)(n + 0) * ldCT + row] = acc.x;
    CT[(size_t)(n + 1) * ldCT + row] = acc.y;
    CT[(size_t)(n + 2) * ldCT + row] = acc.z;
    CT[(size_t)(n + 3) * ldCT + row] = acc.w;
}

// ---------------------------------------------------------------------------
// Kernel 4: norms from the sim partial diagonals. 1 block, 512 threads.
// ---------------------------------------------------------------------------
__global__ void diag_kernel(const float* __restrict__ P) {
    int j = threadIdx.x;
    float s = P[(size_t)j * B_ + j]
            + P[(size_t)B_ * B_ + (size_t)j * B_ + j]
            + P[2 * (size_t)B_ * B_ + (size_t)j * B_ + j];
    g_norm[j] = sqrtf(s);
}

// ---------------------------------------------------------------------------
// Kernel 5: fused sim split-K reduce + cosine + temperature + logsumexp.
// One block (256 threads) per row; 2 logits per thread.
// ---------------------------------------------------------------------------
__global__ __launch_bounds__(256) void lse_kernel(const float* __restrict__ P) {
    const int i = blockIdx.x;
    const int t = threadIdx.x;
    __shared__ float red[256];
    __shared__ float sPos;

    const float ni = g_norm[i];
    const int pc = (i + MH) & (B_ - 1);
    float l[2];
#pragma unroll
    for (int u = 0; u < 2; u++) {
        int j = t + u * 256;
        float s = P[(size_t)i * B_ + j]
                + P[(size_t)B_ * B_ + (size_t)i * B_ + j]
                + P[2 * (size_t)B_ * B_ + (size_t)i * B_ + j];
        float denom = fmaxf(ni * g_norm[j], 1e-8f);
        float c = (s / denom) / 0.1f;
        if (j == pc) sPos = c;
        l[u] = (j == i) ? (-65504.0f / 0.1f) : c;
    }

    float m = fmaxf(l[0], l[1]);
    red[t] = m;
    __syncthreads();
    for (int s = 128; s > 0; s >>= 1) {
        if (t < s) red[t] = fmaxf(red[t], red[t + s]);
        __syncthreads();
    }
    const float mx = red[0];
    __syncthreads();

    float e = expf(l[0] - mx) + expf(l[1] - mx);
    red[t] = e;
    __syncthreads();
    for (int s = 128; s > 0; s >>= 1) {
        if (t < s) red[t] += red[t + s];
        __syncthreads();
    }

    if (t == 0) {
        float lse = mx + logf(red[0]);
        g_nll[i] = lse - sPos;
    }
}

// ---------------------------------------------------------------------------
// Kernel 6: deterministic mean over 512 nll values -> scalar output
// ---------------------------------------------------------------------------
__global__ void mean_kernel(float* __restrict__ out) {
    __shared__ float red[512];
    int t = threadIdx.x;
    red[t] = g_nll[t];
    __syncthreads();
    for (int s = 256; s > 0; s >>= 1) {
        if (t < s) red[t] += red[t + s];
        __syncthreads();
    }
    if (t == 0) out[0] = red[0] / (float)B_;
}

// ---------------------------------------------------------------------------
extern "C" void kernel_launch(void* const* d_in, const int* in_sizes, int n_in,
                              void* d_out, int out_size) {
    const float* x   = (const float*)d_in[0];
    const float* W1c = (const float*)d_in[1];
    const float* b1c = (const float*)d_in[2];
    const float* W2c = (const float*)d_in[3];
    const float* b2c = (const float*)d_in[4];
    const float* W1a = (const float*)d_in[5];
    const float* b1a = (const float*)d_in[6];
    const float* W2a = (const float*)d_in[7];
    const float* b2a = (const float*)d_in[8];
    float* out = (float*)d_out;

    float *p_pooled, *p_part1, *p_part2, *p_z, *p_zT;
    cudaGetSymbolAddress((void**)&p_pooled, g_pooled);
    cudaGetSymbolAddress((void**)&p_part1, g_part1);
    cudaGetSymbolAddress((void**)&p_part2, g_part2);
    cudaGetSymbolAddress((void**)&p_z, g_z);
    cudaGetSymbolAddress((void**)&p_zT, g_zT);

    // 1. mean pooling
    pool_kernel<<<dim3(SPLIT, B_), 480>>>(x);
    pool_reduce_kernel<<<B_, 256>>>();

    // 2. layer 1 partials: pooled @ W1. K=960 (KS=4, Kc=240), N=480
    //    grid (8 bn, 8 bm, 2*4) = 512 blocks of 128 thr
    gemm_splitk<<<dim3(8, 8, 2 * 4), 128>>>(p_pooled, W1c, W1a, p_part1,
                                            MH, D_, H1, 240, 4);

    // 3. layer 2 fused (L1 reduce+bias+relu on A). K=480 (KS=5, Kc=96), N=240
    //    grid (4, 8, 10) = 320 blocks
    gemm_l2_fused<<<dim3(4, 8, 2 * 5), 128>>>(p_part1, W2c, W2a, b1c, b1a,
                                              p_part2, MH, H2, 96, 5);

    // 4. reduce L2 partials -> z (+b2) and zT
    reduce_k<<<(B_ * H2 / 4 + 255) / 256, 256>>>(p_part2, p_z, p_zT, b2c, b2a,
                                                 B_, MH, H2, 5, B_);

    // 5. sim partials = z @ zT. K=240 (KS=3, Kc=80), N=512.
    //    grid (8, 16, 3) = 384 blocks
    gemm_splitk<<<dim3(8, 16, 1 * 3), 128>>>(p_z, p_zT, p_zT, p_part1,
                                             B_, H2, B_, 80, 3);

    // 6. norms from partial diagonals; 7. fused reduce+lse; 8. mean
    diag_kernel<<<1, B_>>>(p_part1);
    lse_kernel<<<B_, 256>>>(p_part1);
    mean_kernel<<<1, B_>>>(out);
}